// round 4
// baseline (speedup 1.0000x reference)
#include <cuda_runtime.h>
#include <cuda_fp16.h>
#include <cstdint>
#include <math.h>

// ---------------- problem constants ----------------
#define BATCH    16384
#define F_IN     768
#define F_OUT    512
#define BM       64            // batch rows per CTA
#define BK       64            // K chunk
#define NCHUNK   (F_IN / BK)   // 12 chunks per pass
#define NPASS    2
#define TOTCHUNK (NCHUNK * NPASS)  // 24
#define NTHREADS 512
#define CTAS     (BATCH / BM)  // 256

// ---------------- smem layout (bytes) ----------------
#define SM_BIAS  0                     // 512 f32 = 2048
#define SM_W2    2048                  // 1024 f32 = 4096
#define SM_RED   6144                  // 64 f32 = 256
#define SM_A0    8192                  // 64 rows x 128B = 8192
#define SM_A1    16384
#define SM_B0    24576                 // 512 rows x 128B = 65536
#define SM_B1    90112
#define SM_TOTAL 155648

// ---------------- helpers ----------------
__device__ __forceinline__ uint32_t smem_u32(const void* p) {
    uint32_t a;
    asm("{ .reg .u64 t; cvta.to.shared.u64 t, %1; cvt.u32.u64 %0, t; }" : "=r"(a) : "l"(p));
    return a;
}

#define LDSM_X4(r0, r1, r2, r3, addr) \
    asm volatile("ldmatrix.sync.aligned.m8n8.x4.shared.b16 {%0,%1,%2,%3}, [%4];" \
                 : "=r"(r0), "=r"(r1), "=r"(r2), "=r"(r3) : "r"(addr))

#define MMA16816(d, a, b) \
    asm volatile("mma.sync.aligned.m16n8k16.row.col.f32.f16.f16.f32 " \
                 "{%0,%1,%2,%3}, {%4,%5,%6,%7}, {%8,%9}, {%0,%1,%2,%3};" \
                 : "+f"((d)[0]), "+f"((d)[1]), "+f"((d)[2]), "+f"((d)[3]) \
                 : "r"((a)[0]), "r"((a)[1]), "r"((a)[2]), "r"((a)[3]), \
                   "r"((b)[0]), "r"((b)[1]))

#define CP_ASYNC16(dst, src) \
    asm volatile("cp.async.cg.shared.global [%0], [%1], 16;" :: "r"(dst), "l"(src) : "memory")
#define CP_COMMIT() asm volatile("cp.async.commit_group;" ::: "memory")
#define CP_WAIT0()  asm volatile("cp.async.wait_group 0;" ::: "memory")

// Swizzle<3,4,3>: XOR 16B-chunk index (bits 4-6) with row低3bits (bits 7-9)
__device__ __forceinline__ uint32_t sw128(uint32_t off) {
    return off ^ ((off >> 3) & 0x70);
}

// cvt 8 f32 -> 8 f16, swizzled 16B STS
__device__ __forceinline__ void sts_a16(uint32_t addr, float4 v0, float4 v1) {
    uint32_t u0, u1, u2, u3;
    asm("cvt.rn.f16x2.f32 %0, %1, %2;" : "=r"(u0) : "f"(v0.y), "f"(v0.x));
    asm("cvt.rn.f16x2.f32 %0, %1, %2;" : "=r"(u1) : "f"(v0.w), "f"(v0.z));
    asm("cvt.rn.f16x2.f32 %0, %1, %2;" : "=r"(u2) : "f"(v1.y), "f"(v1.x));
    asm("cvt.rn.f16x2.f32 %0, %1, %2;" : "=r"(u3) : "f"(v1.w), "f"(v1.z));
    asm volatile("st.shared.v4.u32 [%0], {%1,%2,%3,%4};"
                 :: "r"(addr), "r"(u0), "r"(u1), "r"(u2), "r"(u3) : "memory");
}

// ---------------- W1 fp32 -> fp16 pre-conversion ----------------
__device__ __align__(16) __half g_W1h[F_OUT * F_IN];

__global__ void convert_w1_kernel(const float* __restrict__ W1) {
    int i = blockIdx.x * blockDim.x + threadIdx.x;
    const int n = F_OUT * F_IN / 2;
    if (i < n) {
        float2 v = reinterpret_cast<const float2*>(W1)[i];
        reinterpret_cast<__half2*>(g_W1h)[i] = __floats2half2_rn(v.x, v.y);
    }
}

// ---------------- fused perspective-network kernel ----------------
__global__ void __launch_bounds__(NTHREADS, 1)
persp_kernel(const float* __restrict__ stm, const float* __restrict__ nstm,
             const float* __restrict__ b1, const float* __restrict__ W2,
             const float* __restrict__ b2, float* __restrict__ out) {
    extern __shared__ __align__(1024) char smem[];
    const uint32_t sb = smem_u32(smem);
    const int tid  = threadIdx.x;
    const int lane = tid & 31;
    const int wid  = tid >> 5;
    const int warpM = wid >> 3;    // 0..1  (32 rows each)
    const int warpN = wid & 7;     // 0..7  (64 cols each)
    const int m0 = blockIdx.x * BM;

    float* bias_s = reinterpret_cast<float*>(smem + SM_BIAS);
    float* w2_s   = reinterpret_cast<float*>(smem + SM_W2);
    float* red_s  = reinterpret_cast<float*>(smem + SM_RED);

    for (int i = tid; i < F_OUT; i += NTHREADS)     bias_s[i] = b1[i];
    for (int i = tid; i < 2 * F_OUT; i += NTHREADS) w2_s[i]   = W2[i];
    if (tid < BM) red_s[tid] = 0.0f;

    // ---- ldmatrix per-lane geometry ----
    // A (row-major M x K): x4 = 16x16 tile; lane -> (m row, k16 half)
    const int aRow   = warpM * 32 + ((lane >> 3) & 1) * 8 + (lane & 7);
    const int aK16   = (lane >> 4) * 16;
    const uint32_t aOff = aRow * 128;
    const uint32_t aXor = (uint32_t)aK16 ^ ((uint32_t)(aRow & 7) << 4);
    // B (W1h rows = n, cols = k): x4 = two n8 tiles x two k16 halves
    const int bRow   = warpN * 64 + ((lane >> 4) & 1) * 8 + (lane & 7);
    const int bK16   = ((lane >> 3) & 1) * 16;
    const uint32_t bOff = bRow * 128;
    const uint32_t bXor = (uint32_t)bK16 ^ ((uint32_t)(bRow & 7) << 4);

    // ---- global->smem fill geometry ----
    const int aRowG = tid >> 3;             // 0..63
    const int aSeg  = tid & 7;              // 8-float segment
    const uint32_t aSts = aRowG * 128 + (((uint32_t)aSeg * 16) ^ ((uint32_t)(aRowG & 7) << 4));
    const int bRow0 = tid >> 3;             // 0..63, rows bRow0 + 64*j
    const int bSeg  = tid & 7;
    const uint32_t bDstBase = bRow0 * 128 + (((uint32_t)bSeg * 16) ^ ((uint32_t)(bRow0 & 7) << 4));
    const __half* bSrcBase = g_W1h + (size_t)bRow0 * F_IN + bSeg * 8;

    float acc[2][8][4] = {};
    float rowsum[4] = {0.f, 0.f, 0.f, 0.f};
    float4 sA0, sA1;   // staged A regs (chunk g+1)

    // ---- prologue: fill buf0 (chunk 0), stage A(chunk 1) ----
    {
        const uint32_t bufB = sb + SM_B0;
#pragma unroll
        for (int j = 0; j < 8; ++j)
            CP_ASYNC16(bufB + bDstBase + j * 8192, bSrcBase + (size_t)j * 64 * F_IN);
        CP_COMMIT();
        const float4* s0 = reinterpret_cast<const float4*>(
            stm + (size_t)(m0 + aRowG) * F_IN + aSeg * 8);
        sts_a16(sb + SM_A0 + aSts, s0[0], s0[1]);
        const float4* s1 = reinterpret_cast<const float4*>(
            stm + (size_t)(m0 + aRowG) * F_IN + 1 * BK + aSeg * 8);
        sA0 = s1[0]; sA1 = s1[1];
        CP_WAIT0();
        __syncthreads();
    }

    for (int g = 0; g < TOTCHUNK; ++g) {
        const int p = g & 1;
        const uint32_t bufA  = sb + (p ? SM_A1 : SM_A0);
        const uint32_t bufB  = sb + (p ? SM_B1 : SM_B0);
        const uint32_t bufAn = sb + (p ? SM_A0 : SM_A1);
        const uint32_t bufBn = sb + (p ? SM_B0 : SM_B1);

        // prefetch chunk g+1: staged A -> smem, B via cp.async
        if (g + 1 < TOTCHUNK) {
            sts_a16(bufAn + aSts, sA0, sA1);
            const int c1 = (g + 1) % NCHUNK;
            const __half* src = bSrcBase + c1 * BK;
#pragma unroll
            for (int j = 0; j < 8; ++j)
                CP_ASYNC16(bufBn + bDstBase + j * 8192, src + (size_t)j * 64 * F_IN);
            CP_COMMIT();
        }
        // LDG chunk g+2 into staging (lands during compute)
        if (g + 2 < TOTCHUNK) {
            const int g2 = g + 2;
            const float* X = (g2 >= NCHUNK) ? nstm : stm;
            const int c2 = g2 % NCHUNK;
            const float4* s = reinterpret_cast<const float4*>(
                X + (size_t)(m0 + aRowG) * F_IN + c2 * BK + aSeg * 8);
            sA0 = s[0]; sA1 = s[1];
        }

        // ---- compute chunk g from buf p ----
#pragma unroll
        for (int ks = 0; ks < 4; ++ks) {
            const uint32_t kx = (uint32_t)(ks << 5);
            uint32_t a0[4], a1[4];
            LDSM_X4(a0[0], a0[1], a0[2], a0[3], bufA + aOff +        (aXor ^ kx));
            LDSM_X4(a1[0], a1[1], a1[2], a1[3], bufA + aOff + 2048 + (aXor ^ kx));
            uint32_t b[8][2];
#pragma unroll
            for (int nt2 = 0; nt2 < 4; ++nt2) {
                uint32_t r0, r1, r2, r3;
                LDSM_X4(r0, r1, r2, r3, bufB + bOff + nt2 * 2048 + (bXor ^ kx));
                b[nt2 * 2][0] = r0; b[nt2 * 2][1] = r1;
                b[nt2 * 2 + 1][0] = r2; b[nt2 * 2 + 1][1] = r3;
            }
#pragma unroll
            for (int nt = 0; nt < 8; ++nt) {
                MMA16816(acc[0][nt], a0, b[nt]);
                MMA16816(acc[1][nt], a1, b[nt]);
            }
        }

        // ---- end-of-pass epilogue: bias + clip + W2 partial dot, reset acc ----
        if (g == NCHUNK - 1 || g == TOTCHUNK - 1) {
            const int pass = (g >= NCHUNK);
            const int w2o = pass * F_OUT;
#pragma unroll
            for (int mt = 0; mt < 2; ++mt) {
#pragma unroll
                for (int nt = 0; nt < 8; ++nt) {
                    const int nb = warpN * 64 + nt * 8 + (lane & 3) * 2;
                    const float ba = bias_s[nb],      bb = bias_s[nb + 1];
                    const float wa = w2_s[w2o + nb],  wb = w2_s[w2o + nb + 1];
                    float h;
                    h = fminf(fmaxf(acc[mt][nt][0] + ba, 0.f), 1.f); rowsum[mt*2+0] = fmaf(h, wa, rowsum[mt*2+0]);
                    h = fminf(fmaxf(acc[mt][nt][1] + bb, 0.f), 1.f); rowsum[mt*2+0] = fmaf(h, wb, rowsum[mt*2+0]);
                    h = fminf(fmaxf(acc[mt][nt][2] + ba, 0.f), 1.f); rowsum[mt*2+1] = fmaf(h, wa, rowsum[mt*2+1]);
                    h = fminf(fmaxf(acc[mt][nt][3] + bb, 0.f), 1.f); rowsum[mt*2+1] = fmaf(h, wb, rowsum[mt*2+1]);
                    acc[mt][nt][0] = 0.f; acc[mt][nt][1] = 0.f;
                    acc[mt][nt][2] = 0.f; acc[mt][nt][3] = 0.f;
                }
            }
        }

        CP_WAIT0();
        __syncthreads();
    }

    // ---- cross-lane + cross-warp reduce, sigmoid, store ----
#pragma unroll
    for (int r = 0; r < 4; ++r) {
        float v = rowsum[r];
        v += __shfl_xor_sync(0xFFFFFFFFu, v, 1);
        v += __shfl_xor_sync(0xFFFFFFFFu, v, 2);
        if ((lane & 3) == 0) {
            // rowsum[r] with r = mt*2 + half8 -> row = warpM*32 + mt*16 + half8*8 + lane/4
            const int row = warpM * 32 + (r >> 1) * 16 + (r & 1) * 8 + (lane >> 2);
            atomicAdd(&red_s[row], v);
        }
    }
    __syncthreads();
    if (tid < BM) {
        const float z = red_s[tid] + b2[0];
        out[m0 + tid] = 1.0f / (1.0f + expf(-z));
    }
}

// ---------------- launch ----------------
extern "C" void kernel_launch(void* const* d_in, const int* in_sizes, int n_in,
                              void* d_out, int out_size) {
    const float* stm  = (const float*)d_in[0];
    const float* nstm = (const float*)d_in[1];
    const float* W1   = (const float*)d_in[2];
    const float* b1   = (const float*)d_in[3];
    const float* W2   = (const float*)d_in[4];
    const float* b2   = (const float*)d_in[5];
    float* out = (float*)d_out;

    cudaFuncSetAttribute(persp_kernel, cudaFuncAttributeMaxDynamicSharedMemorySize, SM_TOTAL);

    const int nconv = F_OUT * F_IN / 2;
    convert_w1_kernel<<<(nconv + 255) / 256, 256>>>(W1);
    persp_kernel<<<CTAS, NTHREADS, SM_TOTAL>>>(stm, nstm, b1, W2, b2, out);
}